// round 3
// baseline (speedup 1.0000x reference)
#include <cuda_runtime.h>

#define BB 1024
#define FF 39
#define KK 16
#define PP 741
#define TT 9139
#define ROWP 20                       // padded smem row stride (floats)
#define NTHR 256
#define CH   ((TT + NTHR - 1) / NTHR) // 36 triples per thread (contiguous)

// ---- device-global scratch (no allocations allowed) ----
__device__ float g_L2[BB * PP];                 // ~3.0 MB
__device__ float g_L3[(size_t)BB * TT];         // ~37.4 MB (fits in L2)
__device__ float g_lin[BB];
__device__ float g_c2[PP], g_o2[PP];
__device__ float g_c3[TT], g_o3[TT];
__device__ int   g_tri[TT];

// ---------------------------------------------------------------------------
// Kernel 0: pack triple indices into one word (i<39 fits in 6 bits)
// ---------------------------------------------------------------------------
__global__ void pack_tri(const int* __restrict__ i1, const int* __restrict__ i2,
                         const int* __restrict__ i3) {
    int t = blockIdx.x * blockDim.x + threadIdx.x;
    if (t < TT) g_tri[t] = i1[t] | (i2[t] << 6) | (i3[t] << 12);
}

// ---------------------------------------------------------------------------
// Kernel A: per-batch-row gather + level2 + level3 (one CTA per b)
// ---------------------------------------------------------------------------
__global__ __launch_bounds__(NTHR) void compute_levels(
    const int*   __restrict__ feats,
    const float* __restrict__ w,
    const float* __restrict__ v,
    const int*   __restrict__ rows,
    const int*   __restrict__ cols)
{
    __shared__ int   sidx[FF];
    __shared__ float sxv[FF * ROWP];
    __shared__ float stage[CH * NTHR];   // 9216 words: indices, then results

    const int b   = blockIdx.x;
    const int tid = threadIdx.x;

    if (tid < FF) sidx[tid] = feats[b * FF + tid];
    __syncthreads();

    // gather embeddings into padded smem tile
    for (int e = tid; e < FF * KK; e += NTHR) {
        int f = e >> 4, k = e & 15;
        sxv[f * ROWP + k] = v[(size_t)sidx[f] * KK + k];
    }
    // cooperative coalesced load of packed triple indices into stage
    int* stagei = (int*)stage;
    for (int t = tid; t < TT; t += NTHR) stagei[t] = g_tri[t];
    // linear term (warp 0)
    if (tid < 32) {
        float s = 0.f;
        for (int f = tid; f < FF; f += 32) s += w[sidx[f]];
        #pragma unroll
        for (int o = 16; o; o >>= 1) s += __shfl_down_sync(0xffffffffu, s, o);
        if (tid == 0) g_lin[b] = s;
    }
    __syncthreads();

    // ---- level2: coalesced per-thread columns ----
    for (int p = tid; p < PP; p += NTHR) {
        int r = rows[p], c = cols[p];
        const float* er = &sxv[r * ROWP];
        const float* ec = &sxv[c * ROWP];
        float s = 0.f;
        #pragma unroll
        for (int k = 0; k < KK; k++) s += er[k] * ec[k];
        g_L2[b * PP + p] = s;
    }

    // ---- level3: contiguous chunk per thread, register-cache e1 and e1*e2 ----
    {
        const int t0 = tid * CH;
        const int t1 = (t0 + CH < TT) ? (t0 + CH) : TT;
        int la = -1, lb = -1;
        float e1[KK], e12[KK];
        for (int t = t0; t < t1; t++) {
            int pk = stagei[t];
            int a  = pk & 63;
            int b2 = (pk >> 6) & 63;
            int c  = (pk >> 12) & 63;
            if (a != la) {
                #pragma unroll
                for (int k = 0; k < KK; k++) e1[k] = sxv[a * ROWP + k];
                la = a; lb = -1;
            }
            if (b2 != lb) {
                const float* e2 = &sxv[b2 * ROWP];
                #pragma unroll
                for (int k = 0; k < KK; k++) e12[k] = e1[k] * e2[k];
                lb = b2;
            }
            const float* e3 = &sxv[c * ROWP];
            float s = 0.f;
            #pragma unroll
            for (int k = 0; k < KK; k++) s += e12[k] * e3[k];
            stage[t] = s;   // overwrite own index slot (read-before-write per thread)
        }
    }
    __syncthreads();

    // coalesced flush of the whole row
    {
        float* dst = &g_L3[(size_t)b * TT];
        for (int t = tid; t < TT; t += NTHR) dst[t] = stage[t];
    }
}

// ---------------------------------------------------------------------------
// Kernel B: per-column batch stats -> affine coefficients (c, o)
// layout: 32 columns x 8 batch-lanes per 256-thread CTA
// ---------------------------------------------------------------------------
__global__ __launch_bounds__(NTHR) void stats3(
    const float* __restrict__ gamma, const float* __restrict__ beta,
    const float* __restrict__ gw)
{
    __shared__ float ssum[NTHR], ssq[NTHR];
    const int tx = threadIdx.x & 31;
    const int ty = threadIdx.x >> 5;   // 0..7
    const int t  = blockIdx.x * 32 + tx;
    float s = 0.f, q = 0.f;
    if (t < TT) {
        #pragma unroll 4
        for (int bb = ty; bb < BB; bb += 8) {
            float x = g_L3[(size_t)bb * TT + t];
            s += x; q += x * x;
        }
    }
    ssum[threadIdx.x] = s; ssq[threadIdx.x] = q;
    __syncthreads();
    if (ty == 0 && t < TT) {
        #pragma unroll
        for (int j = 1; j < 8; j++) { s += ssum[j * 32 + tx]; q += ssq[j * 32 + tx]; }
        float mean = s * (1.0f / BB);
        float var  = q * (1.0f / BB) - mean * mean;
        float inv  = rsqrtf(var + 1e-3f);
        float c    = gamma[t] * gw[t] * inv;
        g_c3[t] = c;
        g_o3[t] = beta[t] * gw[t] - c * mean;
    }
}

__global__ __launch_bounds__(NTHR) void stats2(
    const float* __restrict__ gamma, const float* __restrict__ beta,
    const float* __restrict__ gw)
{
    __shared__ float ssum[NTHR], ssq[NTHR];
    const int tx = threadIdx.x & 31;
    const int ty = threadIdx.x >> 5;
    const int p  = blockIdx.x * 32 + tx;
    float s = 0.f, q = 0.f;
    if (p < PP) {
        #pragma unroll 4
        for (int bb = ty; bb < BB; bb += 8) {
            float x = g_L2[bb * PP + p];
            s += x; q += x * x;
        }
    }
    ssum[threadIdx.x] = s; ssq[threadIdx.x] = q;
    __syncthreads();
    if (ty == 0 && p < PP) {
        #pragma unroll
        for (int j = 1; j < 8; j++) { s += ssum[j * 32 + tx]; q += ssq[j * 32 + tx]; }
        float mean = s * (1.0f / BB);
        float var  = q * (1.0f / BB) - mean * mean;
        float inv  = rsqrtf(var + 1e-3f);
        float c    = gamma[p] * gw[p] * inv;
        g_c2[p] = c;
        g_o2[p] = beta[p] * gw[p] - c * mean;
    }
}

// ---------------------------------------------------------------------------
// Kernel C: weighted row reduction -> logits
// ---------------------------------------------------------------------------
__global__ __launch_bounds__(NTHR) void final_reduce(
    const float* __restrict__ bias, float* __restrict__ out)
{
    const int b   = blockIdx.x;
    const int tid = threadIdx.x;
    const float* L3 = &g_L3[(size_t)b * TT];
    const float* L2 = &g_L2[b * PP];

    float acc = 0.f;
    for (int t = tid; t < TT; t += NTHR)
        acc += g_c3[t] * L3[t] + g_o3[t];
    for (int p = tid; p < PP; p += NTHR)
        acc += g_c2[p] * L2[p] + g_o2[p];

    #pragma unroll
    for (int o = 16; o; o >>= 1) acc += __shfl_down_sync(0xffffffffu, acc, o);
    __shared__ float red[8];
    if ((tid & 31) == 0) red[tid >> 5] = acc;
    __syncthreads();
    if (tid == 0) {
        float s = 0.f;
        #pragma unroll
        for (int j = 0; j < 8; j++) s += red[j];
        out[b] = s + g_lin[b] + bias[0];
    }
}

// ---------------------------------------------------------------------------
extern "C" void kernel_launch(void* const* d_in, const int* in_sizes, int n_in,
                              void* d_out, int out_size)
{
    const int*   feats  = (const int*)  d_in[0];
    const float* w      = (const float*)d_in[1];
    const float* v      = (const float*)d_in[2];
    const float* bias   = (const float*)d_in[3];
    const float* gamma2 = (const float*)d_in[4];
    const float* beta2  = (const float*)d_in[5];
    const float* gw2    = (const float*)d_in[6];
    const float* gamma3 = (const float*)d_in[7];
    const float* beta3  = (const float*)d_in[8];
    const float* gw3    = (const float*)d_in[9];
    const int*   rows   = (const int*)  d_in[10];
    const int*   cols   = (const int*)  d_in[11];
    const int*   i1     = (const int*)  d_in[12];
    const int*   i2     = (const int*)  d_in[13];
    const int*   i3     = (const int*)  d_in[14];
    float* out = (float*)d_out;

    pack_tri<<<(TT + NTHR - 1) / NTHR, NTHR>>>(i1, i2, i3);
    compute_levels<<<BB, NTHR>>>(feats, w, v, rows, cols);
    stats2<<<(PP + 31) / 32, NTHR>>>(gamma2, beta2, gw2);
    stats3<<<(TT + 31) / 32, NTHR>>>(gamma3, beta3, gw3);
    final_reduce<<<BB, NTHR>>>(bias, out);
}

// round 5
// speedup vs baseline: 1.9711x; 1.9711x over previous
#include <cuda_runtime.h>

#define BB   1024
#define FF   39
#define KK   16
#define PP   741
#define PPP  768                      // padded L2 row stride
#define TT   9139
#define TTP  9216                     // padded L3 row stride (72*128)
#define ROWP 20                       // padded embedding row stride (floats)
#define NTHR 256

// ---- device-global scratch (no allocations allowed) ----
__device__ float g_L2[BB * PPP];                // ~3.1 MB
__device__ float g_L3[(size_t)BB * TTP];        // ~37.7 MB (L2-resident)
__device__ float g_lin[BB];
__device__ float g_c2[PP], g_o2[PP];
__device__ float g_c3[TT], g_o3[TT];
__device__ int   g_tri[TT];                     // pair_idx | (c<<16)
__device__ float g_sumo2, g_sumo3;

// ---------------------------------------------------------------------------
// Kernel 0: map triple -> (pair index, third element); reset offset sums
// ---------------------------------------------------------------------------
__global__ void pack_tri(const int* __restrict__ i1, const int* __restrict__ i2,
                         const int* __restrict__ i3) {
    int t = blockIdx.x * blockDim.x + threadIdx.x;
    if (t < TT) {
        int a = i1[t], b2 = i2[t], c = i3[t];
        int p = a * (FF - 1) - (a * (a - 1)) / 2 + (b2 - a - 1); // lexicographic pair idx
        g_tri[t] = p | (c << 16);
    }
    if (blockIdx.x == 0 && threadIdx.x == 0) { g_sumo2 = 0.f; g_sumo3 = 0.f; }
}

// ---------------------------------------------------------------------------
// Kernel A: per-batch-row gather + pair products + level2 + level3 (branch-free)
// dynamic smem: P2[PP*KK] then sxv[FF*ROWP]
// ---------------------------------------------------------------------------
__global__ __launch_bounds__(NTHR) void compute_levels(
    const int*   __restrict__ feats,
    const float* __restrict__ w,
    const float* __restrict__ v,
    const int*   __restrict__ rows,
    const int*   __restrict__ cols)
{
    extern __shared__ float dsm[];
    float* P2  = dsm;                // 741*16 floats
    float* sxv = dsm + PP * KK;      // 39*20 floats
    __shared__ int sidx[FF];

    const int b   = blockIdx.x;
    const int tid = threadIdx.x;

    if (tid < FF) sidx[tid] = feats[b * FF + tid];
    __syncthreads();

    for (int e = tid; e < FF * KK; e += NTHR) {
        int f = e >> 4, k = e & 15;
        sxv[f * ROWP + k] = v[(size_t)sidx[f] * KK + k];
    }
    if (tid < 32) {
        float s = 0.f;
        for (int f = tid; f < FF; f += 32) s += w[sidx[f]];
        #pragma unroll
        for (int o = 16; o; o >>= 1) s += __shfl_down_sync(0xffffffffu, s, o);
        if (tid == 0) g_lin[b] = s;
    }
    __syncthreads();

    // ---- Phase A: pair products P2[p][k] = e_rows[p] * e_cols[p]; level2 = sum_k ----
    for (int p = tid; p < PP; p += NTHR) {
        int r = rows[p], c = cols[p];
        const float4* er = (const float4*)&sxv[r * ROWP];
        const float4* ec = (const float4*)&sxv[c * ROWP];
        float4* Pq = (float4*)&P2[p * KK];
        float s2 = 0.f;
        #pragma unroll
        for (int q = 0; q < 4; q++) {
            float4 a4 = er[q], b4 = ec[q], m;
            m.x = a4.x * b4.x; m.y = a4.y * b4.y;
            m.z = a4.z * b4.z; m.w = a4.w * b4.w;
            Pq[q] = m;
            s2 += m.x + m.y + m.z + m.w;
        }
        g_L2[b * PPP + p] = s2;
    }
    __syncthreads();

    // ---- Phase B: level3[t] = dot(P2[pair(t)], e_{c(t)}) — branch-free, coalesced ----
    float* dst = g_L3 + (size_t)b * TTP;
    for (int t = tid; t < TT; t += NTHR) {
        int d = __ldg(&g_tri[t]);
        int p = d & 0xFFFF, c = d >> 16;
        const float4* Pp = (const float4*)&P2[p * KK];   // mostly warp-broadcast
        const float4* Ec = (const float4*)&sxv[c * ROWP];
        float s = 0.f;
        #pragma unroll
        for (int q = 0; q < 4; q++) {
            float4 a4 = Pp[q], e4 = Ec[q];
            s += a4.x * e4.x + a4.y * e4.y + a4.z * e4.z + a4.w * e4.w;
        }
        dst[t] = s;
    }
}

// ---------------------------------------------------------------------------
// Kernel B: column batch stats -> affine coefficients; also accumulate sum(o)
// CTA = 32 tx * 8 ty; each tx owns 4 consecutive columns (float4 loads)
// ---------------------------------------------------------------------------
__global__ __launch_bounds__(NTHR) void stats3(
    const float* __restrict__ gamma, const float* __restrict__ beta,
    const float* __restrict__ gw)
{
    __shared__ float4 ss[NTHR], sq[NTHR];
    const int tx = threadIdx.x & 31;
    const int ty = threadIdx.x >> 5;
    const int t0 = blockIdx.x * 128 + tx * 4;

    float4 s = make_float4(0.f, 0.f, 0.f, 0.f);
    float4 q = make_float4(0.f, 0.f, 0.f, 0.f);
    #pragma unroll 8
    for (int b = ty; b < BB; b += 8) {
        float4 x = *(const float4*)(g_L3 + (size_t)b * TTP + t0);
        s.x += x.x; s.y += x.y; s.z += x.z; s.w += x.w;
        q.x += x.x * x.x; q.y += x.y * x.y; q.z += x.z * x.z; q.w += x.w * x.w;
    }
    ss[threadIdx.x] = s; sq[threadIdx.x] = q;
    __syncthreads();

    float osum = 0.f;
    if (ty == 0) {
        #pragma unroll
        for (int j = 1; j < 8; j++) {
            float4 a = ss[j * 32 + tx], c4 = sq[j * 32 + tx];
            s.x += a.x; s.y += a.y; s.z += a.z; s.w += a.w;
            q.x += c4.x; q.y += c4.y; q.z += c4.z; q.w += c4.w;
        }
        float sa[4] = {s.x, s.y, s.z, s.w};
        float qa[4] = {q.x, q.y, q.z, q.w};
        #pragma unroll
        for (int e = 0; e < 4; e++) {
            int t = t0 + e;
            if (t < TT) {
                float mean = sa[e] * (1.0f / BB);
                float var  = qa[e] * (1.0f / BB) - mean * mean;
                float inv  = rsqrtf(var + 1e-3f);
                float cc   = gamma[t] * gw[t] * inv;
                float oo   = beta[t] * gw[t] - cc * mean;
                g_c3[t] = cc; g_o3[t] = oo;
                osum += oo;
            }
        }
        #pragma unroll
        for (int o = 16; o; o >>= 1) osum += __shfl_down_sync(0xffffffffu, osum, o);
        if (tx == 0) atomicAdd(&g_sumo3, osum);
    }
}

__global__ __launch_bounds__(NTHR) void stats2(
    const float* __restrict__ gamma, const float* __restrict__ beta,
    const float* __restrict__ gw)
{
    __shared__ float4 ss[NTHR], sq[NTHR];
    const int tx = threadIdx.x & 31;
    const int ty = threadIdx.x >> 5;
    const int p0 = blockIdx.x * 128 + tx * 4;

    float4 s = make_float4(0.f, 0.f, 0.f, 0.f);
    float4 q = make_float4(0.f, 0.f, 0.f, 0.f);
    #pragma unroll 8
    for (int b = ty; b < BB; b += 8) {
        float4 x = *(const float4*)(g_L2 + b * PPP + p0);
        s.x += x.x; s.y += x.y; s.z += x.z; s.w += x.w;
        q.x += x.x * x.x; q.y += x.y * x.y; q.z += x.z * x.z; q.w += x.w * x.w;
    }
    ss[threadIdx.x] = s; sq[threadIdx.x] = q;
    __syncthreads();

    float osum = 0.f;
    if (ty == 0) {
        #pragma unroll
        for (int j = 1; j < 8; j++) {
            float4 a = ss[j * 32 + tx], c4 = sq[j * 32 + tx];
            s.x += a.x; s.y += a.y; s.z += a.z; s.w += a.w;
            q.x += c4.x; q.y += c4.y; q.z += c4.z; q.w += c4.w;
        }
        float sa[4] = {s.x, s.y, s.z, s.w};
        float qa[4] = {q.x, q.y, q.z, q.w};
        #pragma unroll
        for (int e = 0; e < 4; e++) {
            int p = p0 + e;
            if (p < PP) {
                float mean = sa[e] * (1.0f / BB);
                float var  = qa[e] * (1.0f / BB) - mean * mean;
                float inv  = rsqrtf(var + 1e-3f);
                float cc   = gamma[p] * gw[p] * inv;
                float oo   = beta[p] * gw[p] - cc * mean;
                g_c2[p] = cc; g_o2[p] = oo;
                osum += oo;
            }
        }
        #pragma unroll
        for (int o = 16; o; o >>= 1) osum += __shfl_down_sync(0xffffffffu, osum, o);
        if (tx == 0) atomicAdd(&g_sumo2, osum);
    }
}

// ---------------------------------------------------------------------------
// Kernel C: weighted row reductions -> logits. 8 batch rows per CTA
// (amortizes c3/c2 reads 8x; 9 independent loads per iteration for MLP)
// ---------------------------------------------------------------------------
__global__ __launch_bounds__(NTHR) void final_reduce(
    const float* __restrict__ bias, float* __restrict__ out)
{
    const int b0  = blockIdx.x * 8;
    const int tid = threadIdx.x;
    float acc[8] = {0.f, 0.f, 0.f, 0.f, 0.f, 0.f, 0.f, 0.f};

    for (int t = tid; t < TT; t += NTHR) {
        float w3 = g_c3[t];
        const float* base = g_L3 + (size_t)b0 * TTP + t;
        #pragma unroll
        for (int j = 0; j < 8; j++)
            acc[j] += w3 * base[(size_t)j * TTP];
    }
    for (int p = tid; p < PP; p += NTHR) {
        float w2 = g_c2[p];
        const float* base = g_L2 + b0 * PPP + p;
        #pragma unroll
        for (int j = 0; j < 8; j++)
            acc[j] += w2 * base[j * PPP];
    }

    __shared__ float red[8][8];   // [warp][j]
    #pragma unroll
    for (int j = 0; j < 8; j++) {
        float vsum = acc[j];
        #pragma unroll
        for (int o = 16; o; o >>= 1) vsum += __shfl_down_sync(0xffffffffu, vsum, o);
        if ((tid & 31) == 0) red[tid >> 5][j] = vsum;
    }
    __syncthreads();
    if (tid < 8) {
        float s = 0.f;
        #pragma unroll
        for (int wp = 0; wp < 8; wp++) s += red[wp][tid];
        out[b0 + tid] = s + g_lin[b0 + tid] + bias[0] + g_sumo2 + g_sumo3;
    }
}

// ---------------------------------------------------------------------------
extern "C" void kernel_launch(void* const* d_in, const int* in_sizes, int n_in,
                              void* d_out, int out_size)
{
    const int*   feats  = (const int*)  d_in[0];
    const float* w      = (const float*)d_in[1];
    const float* v      = (const float*)d_in[2];
    const float* bias   = (const float*)d_in[3];
    const float* gamma2 = (const float*)d_in[4];
    const float* beta2  = (const float*)d_in[5];
    const float* gw2    = (const float*)d_in[6];
    const float* gamma3 = (const float*)d_in[7];
    const float* beta3  = (const float*)d_in[8];
    const float* gw3    = (const float*)d_in[9];
    const int*   rows   = (const int*)  d_in[10];
    const int*   cols   = (const int*)  d_in[11];
    const int*   i1     = (const int*)  d_in[12];
    const int*   i2     = (const int*)  d_in[13];
    const int*   i3     = (const int*)  d_in[14];
    float* out = (float*)d_out;

    const int dyn_smem = (PP * KK + FF * ROWP) * (int)sizeof(float);  // ~50.5 KB
    cudaFuncSetAttribute(compute_levels,
                         cudaFuncAttributeMaxDynamicSharedMemorySize, dyn_smem);

    pack_tri<<<(TT + NTHR - 1) / NTHR, NTHR>>>(i1, i2, i3);
    compute_levels<<<BB, NTHR, dyn_smem>>>(feats, w, v, rows, cols);
    stats2<<<PPP / 128, NTHR>>>(gamma2, beta2, gw2);
    stats3<<<TTP / 128, NTHR>>>(gamma3, beta3, gw3);
    final_reduce<<<BB / 8, NTHR>>>(bias, out);
}